// round 13
// baseline (speedup 1.0000x reference)
#include <cuda_runtime.h>
#include <cuda_bf16.h>
#include <mma.h>
#include <math.h>
#include <stdint.h>

using namespace nvcuda;

#define B_ 64
#define T_ 512
#define F_ 64
#define U_ 128
#define G_ 512   // 4*U

#define RGQ 21   // weight quads (4 floats) per thread in registers
#define SGQ 11   // weight quads per thread in smem (RGQ+SGQ = 32)

// ---------------- scratch (static device memory; no allocations) ----------------
__device__ float g_mask[B_ * T_];
__device__ float g_zx[2u * B_ * T_ * G_];               // layer1 then layer2 (reused)
__device__ float g_h1[B_ * T_ * 2 * U_];
__device__ float g_h2[B_ * 2 * U_];
__device__ float g_wq[4 * G_ * U_];                     // scan weights, quad layout
// bf16 split operands for layer-2 tensor-core GEMM
__device__ __nv_bfloat16 g_hh[B_ * T_ * 2 * U_];        // h1 hi   [m][k], ld=256
__device__ __nv_bfloat16 g_hl[B_ * T_ * 2 * U_];        // h1 lo
__device__ __nv_bfloat16 g_b2h[2 * G_ * 2 * U_];        // W2^T hi [dir][n][k], ld=256
__device__ __nv_bfloat16 g_b2l[2 * G_ * 2 * U_];        // W2^T lo
__device__ float g_brep[2 * 16 * G_];                   // bias replicated [dir][16][512]

// ---------------- helpers ----------------
#define FMA2(acc, a, b) asm("fma.rn.f32x2 %0, %1, %2, %0;" : "+l"(acc) : "l"(a), "l"(b))

__device__ __forceinline__ float f32x2_sum(unsigned long long v) {
    unsigned lo, hi;
    asm("mov.b64 {%0, %1}, %2;" : "=r"(lo), "=r"(hi) : "l"(v));
    return __uint_as_float(lo) + __uint_as_float(hi);
}
__device__ __forceinline__ unsigned short bf16bits(float f) {
    __nv_bfloat16 b = __float2bfloat16(f);
    return *(unsigned short*)&b;
}

// ---------------- prep: mask + scan weight quads + W2 split + bias replicate ----------------
__global__ void prep_kernel(const float* __restrict__ x,
                            const float* __restrict__ w1f, const float* __restrict__ w1b,
                            const float* __restrict__ w2f, const float* __restrict__ w2b,
                            const float* __restrict__ w2fi, const float* __restrict__ w2bi,
                            const float* __restrict__ b2f, const float* __restrict__ b2b) {
    int i = blockIdx.x * blockDim.x + threadIdx.x;
    if (i < B_ * T_) {
        const float4* row = (const float4*)(x + (size_t)i * F_);
        bool nz = false;
#pragma unroll
        for (int k = 0; k < F_ / 4; k++) {
            float4 v = row[k];
            nz = nz || (v.x != 0.f) || (v.y != 0.f) || (v.z != 0.f) || (v.w != 0.f);
        }
        g_mask[i] = nz ? 1.f : 0.f;
    }
    int j2 = i - B_ * T_;
    if (j2 >= 0 && j2 < 4 * G_ * U_) {
        int w = j2 >> 16;
        int r = j2 & 65535;
        int k = r >> 9;            // 0..127
        int col = r & 511;         // 0..511
        const float* src = (w == 0) ? w1f : (w == 1) ? w1b : (w == 2) ? w2f : w2b;
        int u = col & 127, gate = col >> 7;
        int q = k >> 5, g = (k >> 2) & 7, e = k & 3;
        g_wq[w * 65536 + ((gate * 8 + g) * 512 + u * 4 + q) * 4 + e] = src[r];
    }
    int j3 = j2 - 4 * G_ * U_;
    if (j3 >= 0 && j3 < 2 * 2 * U_ * G_) {       // W2 input weights: [256][512] x 2 dirs
        int d = j3 >> 17;
        int r = j3 & 131071;
        int k = r >> 9;            // 0..255
        int n = r & 511;           // 0..511
        const float* src = d ? w2bi : w2fi;
        float v = src[r];
        __nv_bfloat16 hi = __float2bfloat16(v);
        float lov = v - __bfloat162float(hi);
        g_b2h[d * 131072 + n * 256 + k] = hi;
        g_b2l[d * 131072 + n * 256 + k] = __float2bfloat16(lov);
    }
    int j4 = j3 - 2 * 2 * U_ * G_;
    if (j4 >= 0 && j4 < 2 * 16 * G_) {           // bias replicated into 16 rows
        int d = j4 >> 13;
        int n = j4 & 511;
        g_brep[j4] = (d ? b2b : b2f)[n];
    }
}

// ---------------- h1 -> bf16 hi/lo split ----------------
__global__ void convert_h1() {
    size_t i = (size_t)blockIdx.x * 256 + threadIdx.x;   // over 2,097,152 float4s
    float4 v = ((const float4*)g_h1)[i];
    ushort4 hh, ll;
    hh.x = bf16bits(v.x); hh.y = bf16bits(v.y); hh.z = bf16bits(v.z); hh.w = bf16bits(v.w);
    float rx = v.x - __bfloat162float(*(__nv_bfloat16*)&hh.x);
    float ry = v.y - __bfloat162float(*(__nv_bfloat16*)&hh.y);
    float rz = v.z - __bfloat162float(*(__nv_bfloat16*)&hh.z);
    float rw = v.w - __bfloat162float(*(__nv_bfloat16*)&hh.w);
    ll.x = bf16bits(rx); ll.y = bf16bits(ry); ll.z = bf16bits(rz); ll.w = bf16bits(rw);
    ((ushort4*)g_hh)[i] = hh;
    ((ushort4*)g_hl)[i] = ll;
}

// ---------------- layer-1 tiled fp32 GEMM with bias (proven version) ----------------
__global__ __launch_bounds__(256) void sgemm_bias(
    const float* __restrict__ A,
    const float* __restrict__ W, const float* __restrict__ bias,
    int dirOff, int M, int N, int K) {
    __shared__ float As[16][132];
    __shared__ float Bs[16][128];
    float* C = g_zx + (size_t)dirOff * B_ * T_ * G_;

    int tid = threadIdx.x;
    int nBase = blockIdx.x * 128;
    int mBase = blockIdx.y * 128;
    int tx = tid & 15, ty = tid >> 4;
    float acc[8][8];
#pragma unroll
    for (int i = 0; i < 8; i++)
#pragma unroll
        for (int j = 0; j < 8; j++) acc[i][j] = 0.f;

    for (int k0 = 0; k0 < K; k0 += 16) {
#pragma unroll
        for (int s = 0; s < 2; s++) {
            int slot = tid + s * 256;
            int row = slot >> 2, c4 = slot & 3;
            float4 v = *(const float4*)(A + (size_t)(mBase + row) * K + k0 + c4 * 4);
            As[c4 * 4 + 0][row] = v.x;
            As[c4 * 4 + 1][row] = v.y;
            As[c4 * 4 + 2][row] = v.z;
            As[c4 * 4 + 3][row] = v.w;
        }
#pragma unroll
        for (int s = 0; s < 2; s++) {
            int slot = tid + s * 256;
            int row = slot >> 5, c4 = slot & 31;
            *(float4*)(&Bs[row][c4 * 4]) =
                *(const float4*)(W + (size_t)(k0 + row) * N + nBase + c4 * 4);
        }
        __syncthreads();
#pragma unroll
        for (int k = 0; k < 16; k++) {
            float a[8], b[8];
            *(float4*)(a)     = *(const float4*)&As[k][ty * 8];
            *(float4*)(a + 4) = *(const float4*)&As[k][ty * 8 + 4];
            *(float4*)(b)     = *(const float4*)&Bs[k][tx * 8];
            *(float4*)(b + 4) = *(const float4*)&Bs[k][tx * 8 + 4];
#pragma unroll
            for (int i = 0; i < 8; i++)
#pragma unroll
                for (int j = 0; j < 8; j++) acc[i][j] = fmaf(a[i], b[j], acc[i][j]);
        }
        __syncthreads();
    }
#pragma unroll
    for (int i = 0; i < 8; i++) {
        int row = mBase + ty * 8 + i;
#pragma unroll
        for (int j = 0; j < 8; j += 4) {
            int col = nBase + tx * 8 + j;
            float4 o;
            o.x = acc[i][j + 0] + bias[col + 0];
            o.y = acc[i][j + 1] + bias[col + 1];
            o.z = acc[i][j + 2] + bias[col + 2];
            o.w = acc[i][j + 3] + bias[col + 3];
            *(float4*)(C + (size_t)row * N + col) = o;
        }
    }
}

// ---------------- layer-2 WMMA bf16 3-term GEMM (sm_80+ path, runs on sm_100) ----------------
// grid (4 N-tiles, 256 M-tiles), 256 threads = 8 warps (4m x 2n).
// Each warp: 32M x 64N via 2x4 m16n16k16 fragments, fp32 accum preloaded with bias.
// D = Ah*Bh + Ah*Bl + Al*Bh ; fragments loaded directly from global (L2-hot B).
__global__ __launch_bounds__(256) void gemm_wmma(
    const __nv_bfloat16* __restrict__ Ah, const __nv_bfloat16* __restrict__ Al,
    const __nv_bfloat16* __restrict__ Bh, const __nv_bfloat16* __restrict__ Bl,
    const float* __restrict__ biasrep,   // [16][512], identical rows
    float* __restrict__ C) {
    int wid = threadIdx.x >> 5;
    int mw = wid & 3, nw = wid >> 2;
    int mBase = blockIdx.y * 128 + mw * 32;
    int nBase = blockIdx.x * 128 + nw * 64;

    wmma::fragment<wmma::accumulator, 16, 16, 16, float> acc[2][4];
#pragma unroll
    for (int i = 0; i < 2; i++)
#pragma unroll
        for (int j = 0; j < 4; j++)
            wmma::load_matrix_sync(acc[i][j], biasrep + nBase + j * 16, G_,
                                   wmma::mem_row_major);

#pragma unroll
    for (int term = 0; term < 3; term++) {
        const __nv_bfloat16* A = (term == 2) ? Al : Ah;
        const __nv_bfloat16* Bm = (term == 1) ? Bl : Bh;
        for (int k = 0; k < 256; k += 16) {
            wmma::fragment<wmma::matrix_a, 16, 16, 16, __nv_bfloat16, wmma::row_major> af[2];
            wmma::fragment<wmma::matrix_b, 16, 16, 16, __nv_bfloat16, wmma::col_major> bf[4];
#pragma unroll
            for (int i = 0; i < 2; i++)
                wmma::load_matrix_sync(af[i], A + (size_t)(mBase + i * 16) * 256 + k, 256);
#pragma unroll
            for (int j = 0; j < 4; j++)
                wmma::load_matrix_sync(bf[j], Bm + (size_t)(nBase + j * 16) * 256 + k, 256);
#pragma unroll
            for (int i = 0; i < 2; i++)
#pragma unroll
                for (int j = 0; j < 4; j++)
                    wmma::mma_sync(acc[i][j], af[i], bf[j], acc[i][j]);
        }
    }
#pragma unroll
    for (int i = 0; i < 2; i++)
#pragma unroll
        for (int j = 0; j < 4; j++)
            wmma::store_matrix_sync(C + (size_t)(mBase + i * 16) * G_ + nBase + j * 16,
                                    acc[i][j], G_, wmma::mem_row_major);
}

// ---------------- recurrent LSTM scan (R10 proven version) ----------------
extern __shared__ float swq[];

__global__ __launch_bounds__(512, 1) void lstm_scan(int layer) {
    int tid = threadIdx.x;
    int dir = blockIdx.x >> 6;
    int b = blockIdx.x & 63;
    int seg = layer * 2 + dir;
    int u = tid >> 2, q = tid & 3;

    __shared__ __align__(16) float hbuf[2][544];

    {
        const float4* src = (const float4*)(g_wq + (size_t)seg * 65536 + RGQ * 2048);
        float4* dst = (float4*)swq;
        for (int j = tid; j < SGQ * 512; j += 512) dst[j] = src[j];
    }
    ulonglong2 wreg[RGQ];
    {
        const float* wb = g_wq + (size_t)seg * 65536 + tid * 4;
#pragma unroll
        for (int m = 0; m < RGQ; m++) wreg[m] = *(const ulonglong2*)(wb + m * 2048);
    }
    for (int j = tid; j < 1088; j += 512) ((float*)hbuf)[j] = 0.f;
    __syncthreads();

    const float* zc = g_zx + ((size_t)dir * B_ + b) * T_ * G_ + q * 128 + u;
    const int mb = b * T_;
    float zpre, mpre;
    {
        int te0 = dir ? (T_ - 1) : 0;
        zpre = zc[(size_t)te0 * G_];
        mpre = g_mask[mb + te0];
    }
    float c_state = 0.f, hprev = 0.f;

    for (int t = 0; t < T_; t++) {
        int te = dir ? (T_ - 1 - t) : t;
        int cur = t & 1, nxt = cur ^ 1;

        float znext = 0.f, mnext = 0.f;
        if (t + 1 < T_) {
            int tn = dir ? (T_ - 2 - t) : (t + 1);
            znext = zc[(size_t)tn * G_];
            mnext = g_mask[mb + tn];
        }

        const float* hc = &hbuf[cur][q * 168];
        const float* swp = swq + tid * 4;
        unsigned long long acc[4] = {0ull, 0ull, 0ull, 0ull};
#pragma unroll
        for (int g = 0; g < 8; g++) {
            ulonglong2 h = *(const ulonglong2*)(hc + 4 * g);
#pragma unroll
            for (int gate = 0; gate < 4; gate++) {
                int m = gate * 8 + g;
                ulonglong2 w;
                if (m < RGQ) w = wreg[m];
                else w = *(const ulonglong2*)(swp + (m - RGQ) * 2048);
                FMA2(acc[gate], w.x, h.x);
                FMA2(acc[gate], w.y, h.y);
            }
        }
        float v0 = f32x2_sum(acc[0]);
        float v1 = f32x2_sum(acc[1]);
        float v2 = f32x2_sum(acc[2]);
        float v3 = f32x2_sum(acc[3]);
        v0 += (q == 0) ? zpre : 0.f;
        v1 += (q == 1) ? zpre : 0.f;
        v2 += (q == 2) ? zpre : 0.f;
        v3 += (q == 3) ? zpre : 0.f;

        v0 += __shfl_xor_sync(0xFFFFFFFFu, v0, 1);
        v1 += __shfl_xor_sync(0xFFFFFFFFu, v1, 1);
        v2 += __shfl_xor_sync(0xFFFFFFFFu, v2, 1);
        v3 += __shfl_xor_sync(0xFFFFFFFFu, v3, 1);
        v0 += __shfl_xor_sync(0xFFFFFFFFu, v0, 2);
        v1 += __shfl_xor_sync(0xFFFFFFFFu, v1, 2);
        v2 += __shfl_xor_sync(0xFFFFFFFFu, v2, 2);
        v3 += __shfl_xor_sync(0xFFFFFFFFu, v3, 2);

        float si = 1.f / (1.f + __expf(-v0));
        float sf = 1.f / (1.f + __expf(-v1));
        float so = 1.f / (1.f + __expf(-v3));
        float cn = sf * c_state + si * tanhf(v2);
        float hn = so * tanhf(cn);
        bool mm = (mpre != 0.f);
        c_state = mm ? cn : c_state;
        float hnew = mm ? hn : hprev;
        hbuf[nxt][q * 136 + u] = hnew;
        if (layer == 0 && q == 0)
            g_h1[((size_t)b * T_ + te) * (2 * U_) + dir * U_ + u] = hnew;
        hprev = hnew;
        zpre = znext;
        mpre = mnext;
        __syncthreads();
    }

    if (layer == 1 && q == 0)
        g_h2[b * (2 * U_) + dir * U_ + u] = hprev;
}

// ---------------- head ----------------
__global__ __launch_bounds__(128) void head_kernel(
    const float* __restrict__ Wd, const float* __restrict__ bd,
    const float* __restrict__ Ws, const float* __restrict__ bs,
    float* __restrict__ out) {
    int b = blockIdx.x, u = threadIdx.x;
    float acc = bd[u];
    const float* h2 = g_h2 + b * (2 * U_);
#pragma unroll 8
    for (int j = 0; j < 2 * U_; j++) acc = fmaf(h2[j], Wd[j * U_ + u], acc);
    acc = fmaxf(acc, 0.f);
    float s = acc * Ws[u];
    __shared__ float red[128];
    red[u] = s;
    __syncthreads();
    for (int off = 64; off; off >>= 1) {
        if (u < off) red[u] += red[u + off];
        __syncthreads();
    }
    if (u == 0) out[b] = 1.f / (1.f + expf(-(red[0] + bs[0])));
}

// ---------------- launch ----------------
extern "C" void kernel_launch(void* const* d_in, const int* in_sizes, int n_in,
                              void* d_out, int out_size) {
    const float* x    = (const float*)d_in[0];
    const float* W1fi = (const float*)d_in[1];
    const float* W1fh = (const float*)d_in[2];
    const float* b1f  = (const float*)d_in[3];
    const float* W1bi = (const float*)d_in[4];
    const float* W1bh = (const float*)d_in[5];
    const float* b1b  = (const float*)d_in[6];
    const float* W2fi = (const float*)d_in[7];
    const float* W2fh = (const float*)d_in[8];
    const float* b2f  = (const float*)d_in[9];
    const float* W2bi = (const float*)d_in[10];
    const float* W2bh = (const float*)d_in[11];
    const float* b2b  = (const float*)d_in[12];
    const float* Wd   = (const float*)d_in[13];
    const float* bd   = (const float*)d_in[14];
    const float* Ws   = (const float*)d_in[15];
    const float* bs   = (const float*)d_in[16];

    const int SWB = SGQ * 2048 * 4;
    static int attrDone = 0;
    if (!attrDone) {
        cudaFuncSetAttribute(lstm_scan, cudaFuncAttributeMaxDynamicSharedMemorySize, SWB);
        attrDone = 1;
    }

    int prepWork = B_ * T_ + 4 * G_ * U_ + 2 * 2 * U_ * G_ + 2 * 16 * G_;
    prep_kernel<<<(prepWork + 255) / 256, 256>>>(x, W1fh, W1bh, W2fh, W2bh,
                                                 W2fi, W2bi, b2f, b2b);

    dim3 ggrid(G_ / 128, (B_ * T_) / 128);  // (4, 256)

    // layer-1 input projections (fp32 FFMA, full precision)
    sgemm_bias<<<ggrid, 256>>>(x, W1fi, b1f, 0, B_ * T_, G_, F_);
    sgemm_bias<<<ggrid, 256>>>(x, W1bi, b1b, 1, B_ * T_, G_, F_);
    lstm_scan<<<128, 512, SWB>>>(0);

    // h1 -> bf16 hi/lo, then layer-2 projections on WMMA tensor cores (3-term split)
    convert_h1<<<8192, 256>>>();

    static void *p_hh = nullptr, *p_hl = nullptr, *p_b2h = nullptr, *p_b2l = nullptr,
                *p_zx = nullptr, *p_br = nullptr;
    if (!p_hh) {
        cudaGetSymbolAddress(&p_hh, g_hh);
        cudaGetSymbolAddress(&p_hl, g_hl);
        cudaGetSymbolAddress(&p_b2h, g_b2h);
        cudaGetSymbolAddress(&p_b2l, g_b2l);
        cudaGetSymbolAddress(&p_zx, g_zx);
        cudaGetSymbolAddress(&p_br, g_brep);
    }
    gemm_wmma<<<ggrid, 256>>>(
        (const __nv_bfloat16*)p_hh, (const __nv_bfloat16*)p_hl,
        (const __nv_bfloat16*)p_b2h, (const __nv_bfloat16*)p_b2l,
        (const float*)p_br, (float*)p_zx);
    gemm_wmma<<<ggrid, 256>>>(
        (const __nv_bfloat16*)p_hh, (const __nv_bfloat16*)p_hl,
        (const __nv_bfloat16*)p_b2h + 131072, (const __nv_bfloat16*)p_b2l + 131072,
        (const float*)p_br + 8192, (float*)p_zx + (size_t)B_ * T_ * G_);
    lstm_scan<<<128, 512, SWB>>>(1);

    head_kernel<<<64, 128>>>(Wd, bd, Ws, bs, (float*)d_out);
}

// round 15
// speedup vs baseline: 1.1552x; 1.1552x over previous
#include <cuda_runtime.h>
#include <cuda_bf16.h>
#include <mma.h>
#include <math.h>
#include <stdint.h>

using namespace nvcuda;

#define B_ 64
#define T_ 512
#define F_ 64
#define U_ 128
#define G_ 512   // 4*U

#define RGQ 21   // weight quads (4 floats) per thread in registers
#define SGQ 11   // weight quads per thread in smem (RGQ+SGQ = 32)

// ---------------- scratch (static device memory; no allocations) ----------------
__device__ float g_mask[B_ * T_];
__device__ float g_zx[2u * B_ * T_ * G_];               // layer1 then layer2 (reused)
__device__ float g_h1[B_ * T_ * 2 * U_];
__device__ float g_h2[B_ * 2 * U_];
__device__ float g_wq[4 * G_ * U_];                     // scan weights, quad layout
// bf16 split operands for layer-2 tensor-core GEMM
__device__ __nv_bfloat16 g_hh[B_ * T_ * 2 * U_];        // h1 hi   [m][k], ld=256
__device__ __nv_bfloat16 g_hl[B_ * T_ * 2 * U_];        // h1 lo
__device__ __nv_bfloat16 g_b2h[2 * G_ * 2 * U_];        // W2^T hi [dir][n][k], ld=256
__device__ __nv_bfloat16 g_b2l[2 * G_ * 2 * U_];        // W2^T lo
__device__ float g_brep[2 * 16 * G_];                   // bias replicated [dir][16][512]

// ---------------- helpers ----------------
#define FMA2(acc, a, b) asm("fma.rn.f32x2 %0, %1, %2, %0;" : "+l"(acc) : "l"(a), "l"(b))

__device__ __forceinline__ float f32x2_sum(unsigned long long v) {
    unsigned lo, hi;
    asm("mov.b64 {%0, %1}, %2;" : "=r"(lo), "=r"(hi) : "l"(v));
    return __uint_as_float(lo) + __uint_as_float(hi);
}
__device__ __forceinline__ unsigned short bf16bits(float f) {
    __nv_bfloat16 b = __float2bfloat16(f);
    return *(unsigned short*)&b;
}

// ---------------- prep: mask + scan weight quads + W2 split + bias replicate ----------------
__global__ void prep_kernel(const float* __restrict__ x,
                            const float* __restrict__ w1f, const float* __restrict__ w1b,
                            const float* __restrict__ w2f, const float* __restrict__ w2b,
                            const float* __restrict__ w2fi, const float* __restrict__ w2bi,
                            const float* __restrict__ b2f, const float* __restrict__ b2b) {
    int i = blockIdx.x * blockDim.x + threadIdx.x;
    if (i < B_ * T_) {
        const float4* row = (const float4*)(x + (size_t)i * F_);
        bool nz = false;
#pragma unroll
        for (int k = 0; k < F_ / 4; k++) {
            float4 v = row[k];
            nz = nz || (v.x != 0.f) || (v.y != 0.f) || (v.z != 0.f) || (v.w != 0.f);
        }
        g_mask[i] = nz ? 1.f : 0.f;
    }
    int j2 = i - B_ * T_;
    if (j2 >= 0 && j2 < 4 * G_ * U_) {
        int w = j2 >> 16;
        int r = j2 & 65535;
        int k = r >> 9;            // 0..127
        int col = r & 511;         // 0..511
        const float* src = (w == 0) ? w1f : (w == 1) ? w1b : (w == 2) ? w2f : w2b;
        int u = col & 127, gate = col >> 7;
        int q = k >> 5, g = (k >> 2) & 7, e = k & 3;
        g_wq[w * 65536 + ((gate * 8 + g) * 512 + u * 4 + q) * 4 + e] = src[r];
    }
    int j3 = j2 - 4 * G_ * U_;
    if (j3 >= 0 && j3 < 2 * 2 * U_ * G_) {       // W2 input weights: [256][512] x 2 dirs
        int d = j3 >> 17;
        int r = j3 & 131071;
        int k = r >> 9;            // 0..255
        int n = r & 511;           // 0..511
        const float* src = d ? w2bi : w2fi;
        float v = src[r];
        __nv_bfloat16 hi = __float2bfloat16(v);
        float lov = v - __bfloat162float(hi);
        g_b2h[d * 131072 + n * 256 + k] = hi;
        g_b2l[d * 131072 + n * 256 + k] = __float2bfloat16(lov);
    }
    int j4 = j3 - 2 * 2 * U_ * G_;
    if (j4 >= 0 && j4 < 2 * 16 * G_) {           // bias replicated into 16 rows
        int d = j4 >> 13;
        int n = j4 & 511;
        g_brep[j4] = (d ? b2b : b2f)[n];
    }
}

// ---------------- h1 -> bf16 hi/lo split ----------------
__global__ void convert_h1() {
    size_t i = (size_t)blockIdx.x * 256 + threadIdx.x;   // over 2,097,152 float4s
    float4 v = ((const float4*)g_h1)[i];
    ushort4 hh, ll;
    hh.x = bf16bits(v.x); hh.y = bf16bits(v.y); hh.z = bf16bits(v.z); hh.w = bf16bits(v.w);
    float rx = v.x - __bfloat162float(*(__nv_bfloat16*)&hh.x);
    float ry = v.y - __bfloat162float(*(__nv_bfloat16*)&hh.y);
    float rz = v.z - __bfloat162float(*(__nv_bfloat16*)&hh.z);
    float rw = v.w - __bfloat162float(*(__nv_bfloat16*)&hh.w);
    ll.x = bf16bits(rx); ll.y = bf16bits(ry); ll.z = bf16bits(rz); ll.w = bf16bits(rw);
    ((ushort4*)g_hh)[i] = hh;
    ((ushort4*)g_hl)[i] = ll;
}

// ---------------- layer-1 tiled fp32 GEMM with bias (proven version) ----------------
__global__ __launch_bounds__(256) void sgemm_bias(
    const float* __restrict__ A,
    const float* __restrict__ W, const float* __restrict__ bias,
    int dirOff, int M, int N, int K) {
    __shared__ float As[16][132];
    __shared__ float Bs[16][128];
    float* C = g_zx + (size_t)dirOff * B_ * T_ * G_;

    int tid = threadIdx.x;
    int nBase = blockIdx.x * 128;
    int mBase = blockIdx.y * 128;
    int tx = tid & 15, ty = tid >> 4;
    float acc[8][8];
#pragma unroll
    for (int i = 0; i < 8; i++)
#pragma unroll
        for (int j = 0; j < 8; j++) acc[i][j] = 0.f;

    for (int k0 = 0; k0 < K; k0 += 16) {
#pragma unroll
        for (int s = 0; s < 2; s++) {
            int slot = tid + s * 256;
            int row = slot >> 2, c4 = slot & 3;
            float4 v = *(const float4*)(A + (size_t)(mBase + row) * K + k0 + c4 * 4);
            As[c4 * 4 + 0][row] = v.x;
            As[c4 * 4 + 1][row] = v.y;
            As[c4 * 4 + 2][row] = v.z;
            As[c4 * 4 + 3][row] = v.w;
        }
#pragma unroll
        for (int s = 0; s < 2; s++) {
            int slot = tid + s * 256;
            int row = slot >> 5, c4 = slot & 31;
            *(float4*)(&Bs[row][c4 * 4]) =
                *(const float4*)(W + (size_t)(k0 + row) * N + nBase + c4 * 4);
        }
        __syncthreads();
#pragma unroll
        for (int k = 0; k < 16; k++) {
            float a[8], b[8];
            *(float4*)(a)     = *(const float4*)&As[k][ty * 8];
            *(float4*)(a + 4) = *(const float4*)&As[k][ty * 8 + 4];
            *(float4*)(b)     = *(const float4*)&Bs[k][tx * 8];
            *(float4*)(b + 4) = *(const float4*)&Bs[k][tx * 8 + 4];
#pragma unroll
            for (int i = 0; i < 8; i++)
#pragma unroll
                for (int j = 0; j < 8; j++) acc[i][j] = fmaf(a[i], b[j], acc[i][j]);
        }
        __syncthreads();
    }
#pragma unroll
    for (int i = 0; i < 8; i++) {
        int row = mBase + ty * 8 + i;
#pragma unroll
        for (int j = 0; j < 8; j += 4) {
            int col = nBase + tx * 8 + j;
            float4 o;
            o.x = acc[i][j + 0] + bias[col + 0];
            o.y = acc[i][j + 1] + bias[col + 1];
            o.z = acc[i][j + 2] + bias[col + 2];
            o.w = acc[i][j + 3] + bias[col + 3];
            *(float4*)(C + (size_t)row * N + col) = o;
        }
    }
}

// ---------------- layer-2 WMMA bf16 3-term GEMM, smem-staged (FIXED staging) ----------------
// grid (4 N-tiles, 256 M-tiles), 256 threads = 8 warps (4m x 2n).
// Each warp: 32M x 64N via 2x4 m16n16k16 fragments, fp32 accum preloaded with bias.
// D = Ah*Bh + Ah*Bl + Al*Bh ; per (term, k-chunk): stage A[128][64] + B[128][64]
// bf16 chunks into padded smem (ld=72) with LINEAR fully-coalesced uint4 mapping:
// j = tid + s*256 over 1024 uint4s, row = j>>3, slot = j&7 (every slot written once).
__global__ __launch_bounds__(256) void gemm_wmma(
    const __nv_bfloat16* __restrict__ Ah, const __nv_bfloat16* __restrict__ Al,
    const __nv_bfloat16* __restrict__ Bh, const __nv_bfloat16* __restrict__ Bl,
    const float* __restrict__ biasrep,   // [16][512], identical rows
    float* __restrict__ C) {
    __shared__ __align__(16) __nv_bfloat16 sA[128][72];
    __shared__ __align__(16) __nv_bfloat16 sB[128][72];

    int tid = threadIdx.x;
    int wid = tid >> 5;
    int mw = wid & 3, nw = wid >> 2;
    int mBase = blockIdx.y * 128;
    int nBase = blockIdx.x * 128;
    int mW = mw * 32, nW = nw * 64;

    wmma::fragment<wmma::accumulator, 16, 16, 16, float> acc[2][4];
#pragma unroll
    for (int i = 0; i < 2; i++)
#pragma unroll
        for (int j = 0; j < 4; j++)
            wmma::load_matrix_sync(acc[i][j], biasrep + nBase + nW + j * 16, G_,
                                   wmma::mem_row_major);

#pragma unroll
    for (int term = 0; term < 3; term++) {
        const __nv_bfloat16* A = (term == 2) ? Al : Ah;
        const __nv_bfloat16* Bm = (term == 1) ? Bl : Bh;
        for (int kc = 0; kc < 4; kc++) {
            int k0 = kc * 64;
            // stage: 1024 uint4 per matrix, linear coalesced mapping
#pragma unroll
            for (int s = 0; s < 4; s++) {
                int j = tid + s * 256;
                int row = j >> 3, slot = j & 7;
                *((uint4*)(&sA[row][0]) + slot) =
                    *((const uint4*)(A + (size_t)(mBase + row) * 256 + k0) + slot);
                *((uint4*)(&sB[row][0]) + slot) =
                    *((const uint4*)(Bm + (size_t)(nBase + row) * 256 + k0) + slot);
            }
            __syncthreads();
#pragma unroll
            for (int kk = 0; kk < 4; kk++) {
                wmma::fragment<wmma::matrix_a, 16, 16, 16, __nv_bfloat16,
                               wmma::row_major> af[2];
                wmma::fragment<wmma::matrix_b, 16, 16, 16, __nv_bfloat16,
                               wmma::col_major> bf[4];
#pragma unroll
                for (int i = 0; i < 2; i++)
                    wmma::load_matrix_sync(af[i], &sA[mW + i * 16][kk * 16], 72);
#pragma unroll
                for (int j = 0; j < 4; j++)
                    wmma::load_matrix_sync(bf[j], &sB[nW + j * 16][kk * 16], 72);
#pragma unroll
                for (int i = 0; i < 2; i++)
#pragma unroll
                    for (int j = 0; j < 4; j++)
                        wmma::mma_sync(acc[i][j], af[i], bf[j], acc[i][j]);
            }
            __syncthreads();
        }
    }
#pragma unroll
    for (int i = 0; i < 2; i++)
#pragma unroll
        for (int j = 0; j < 4; j++)
            wmma::store_matrix_sync(
                C + (size_t)(mBase + mW + i * 16) * G_ + nBase + nW + j * 16,
                acc[i][j], G_, wmma::mem_row_major);
}

// ---------------- recurrent LSTM scan (R10 proven version) ----------------
extern __shared__ float swq[];

__global__ __launch_bounds__(512, 1) void lstm_scan(int layer) {
    int tid = threadIdx.x;
    int dir = blockIdx.x >> 6;
    int b = blockIdx.x & 63;
    int seg = layer * 2 + dir;
    int u = tid >> 2, q = tid & 3;

    __shared__ __align__(16) float hbuf[2][544];

    {
        const float4* src = (const float4*)(g_wq + (size_t)seg * 65536 + RGQ * 2048);
        float4* dst = (float4*)swq;
        for (int j = tid; j < SGQ * 512; j += 512) dst[j] = src[j];
    }
    ulonglong2 wreg[RGQ];
    {
        const float* wb = g_wq + (size_t)seg * 65536 + tid * 4;
#pragma unroll
        for (int m = 0; m < RGQ; m++) wreg[m] = *(const ulonglong2*)(wb + m * 2048);
    }
    for (int j = tid; j < 1088; j += 512) ((float*)hbuf)[j] = 0.f;
    __syncthreads();

    const float* zc = g_zx + ((size_t)dir * B_ + b) * T_ * G_ + q * 128 + u;
    const int mb = b * T_;
    float zpre, mpre;
    {
        int te0 = dir ? (T_ - 1) : 0;
        zpre = zc[(size_t)te0 * G_];
        mpre = g_mask[mb + te0];
    }
    float c_state = 0.f, hprev = 0.f;

    for (int t = 0; t < T_; t++) {
        int te = dir ? (T_ - 1 - t) : t;
        int cur = t & 1, nxt = cur ^ 1;

        float znext = 0.f, mnext = 0.f;
        if (t + 1 < T_) {
            int tn = dir ? (T_ - 2 - t) : (t + 1);
            znext = zc[(size_t)tn * G_];
            mnext = g_mask[mb + tn];
        }

        const float* hc = &hbuf[cur][q * 168];
        const float* swp = swq + tid * 4;
        unsigned long long acc[4] = {0ull, 0ull, 0ull, 0ull};
#pragma unroll
        for (int g = 0; g < 8; g++) {
            ulonglong2 h = *(const ulonglong2*)(hc + 4 * g);
#pragma unroll
            for (int gate = 0; gate < 4; gate++) {
                int m = gate * 8 + g;
                ulonglong2 w;
                if (m < RGQ) w = wreg[m];
                else w = *(const ulonglong2*)(swp + (m - RGQ) * 2048);
                FMA2(acc[gate], w.x, h.x);
                FMA2(acc[gate], w.y, h.y);
            }
        }
        float v0 = f32x2_sum(acc[0]);
        float v1 = f32x2_sum(acc[1]);
        float v2 = f32x2_sum(acc[2]);
        float v3 = f32x2_sum(acc[3]);
        v0 += (q == 0) ? zpre : 0.f;
        v1 += (q == 1) ? zpre : 0.f;
        v2 += (q == 2) ? zpre : 0.f;
        v3 += (q == 3) ? zpre : 0.f;

        v0 += __shfl_xor_sync(0xFFFFFFFFu, v0, 1);
        v1 += __shfl_xor_sync(0xFFFFFFFFu, v1, 1);
        v2 += __shfl_xor_sync(0xFFFFFFFFu, v2, 1);
        v3 += __shfl_xor_sync(0xFFFFFFFFu, v3, 1);
        v0 += __shfl_xor_sync(0xFFFFFFFFu, v0, 2);
        v1 += __shfl_xor_sync(0xFFFFFFFFu, v1, 2);
        v2 += __shfl_xor_sync(0xFFFFFFFFu, v2, 2);
        v3 += __shfl_xor_sync(0xFFFFFFFFu, v3, 2);

        float si = 1.f / (1.f + __expf(-v0));
        float sf = 1.f / (1.f + __expf(-v1));
        float so = 1.f / (1.f + __expf(-v3));
        float cn = sf * c_state + si * tanhf(v2);
        float hn = so * tanhf(cn);
        bool mm = (mpre != 0.f);
        c_state = mm ? cn : c_state;
        float hnew = mm ? hn : hprev;
        hbuf[nxt][q * 136 + u] = hnew;
        if (layer == 0 && q == 0)
            g_h1[((size_t)b * T_ + te) * (2 * U_) + dir * U_ + u] = hnew;
        hprev = hnew;
        zpre = znext;
        mpre = mnext;
        __syncthreads();
    }

    if (layer == 1 && q == 0)
        g_h2[b * (2 * U_) + dir * U_ + u] = hprev;
}

// ---------------- head ----------------
__global__ __launch_bounds__(128) void head_kernel(
    const float* __restrict__ Wd, const float* __restrict__ bd,
    const float* __restrict__ Ws, const float* __restrict__ bs,
    float* __restrict__ out) {
    int b = blockIdx.x, u = threadIdx.x;
    float acc = bd[u];
    const float* h2 = g_h2 + b * (2 * U_);
#pragma unroll 8
    for (int j = 0; j < 2 * U_; j++) acc = fmaf(h2[j], Wd[j * U_ + u], acc);
    acc = fmaxf(acc, 0.f);
    float s = acc * Ws[u];
    __shared__ float red[128];
    red[u] = s;
    __syncthreads();
    for (int off = 64; off; off >>= 1) {
        if (u < off) red[u] += red[u + off];
        __syncthreads();
    }
    if (u == 0) out[b] = 1.f / (1.f + expf(-(red[0] + bs[0])));
}

// ---------------- launch ----------------
extern "C" void kernel_launch(void* const* d_in, const int* in_sizes, int n_in,
                              void* d_out, int out_size) {
    const float* x    = (const float*)d_in[0];
    const float* W1fi = (const float*)d_in[1];
    const float* W1fh = (const float*)d_in[2];
    const float* b1f  = (const float*)d_in[3];
    const float* W1bi = (const float*)d_in[4];
    const float* W1bh = (const float*)d_in[5];
    const float* b1b  = (const float*)d_in[6];
    const float* W2fi = (const float*)d_in[7];
    const float* W2fh = (const float*)d_in[8];
    const float* b2f  = (const float*)d_in[9];
    const float* W2bi = (const float*)d_in[10];
    const float* W2bh = (const float*)d_in[11];
    const float* b2b  = (const float*)d_in[12];
    const float* Wd   = (const float*)d_in[13];
    const float* bd   = (const float*)d_in[14];
    const float* Ws   = (const float*)d_in[15];
    const float* bs   = (const float*)d_in[16];

    const int SWB = SGQ * 2048 * 4;
    static int attrDone = 0;
    if (!attrDone) {
        cudaFuncSetAttribute(lstm_scan, cudaFuncAttributeMaxDynamicSharedMemorySize, SWB);
        attrDone = 1;
    }

    int prepWork = B_ * T_ + 4 * G_ * U_ + 2 * 2 * U_ * G_ + 2 * 16 * G_;
    prep_kernel<<<(prepWork + 255) / 256, 256>>>(x, W1fh, W1bh, W2fh, W2bh,
                                                 W2fi, W2bi, b2f, b2b);

    dim3 ggrid(G_ / 128, (B_ * T_) / 128);  // (4, 256)

    // layer-1 input projections (fp32 FFMA, full precision)
    sgemm_bias<<<ggrid, 256>>>(x, W1fi, b1f, 0, B_ * T_, G_, F_);
    sgemm_bias<<<ggrid, 256>>>(x, W1bi, b1b, 1, B_ * T_, G_, F_);
    lstm_scan<<<128, 512, SWB>>>(0);

    // h1 -> bf16 hi/lo, then layer-2 projections on WMMA tensor cores (3-term split)
    convert_h1<<<8192, 256>>>();

    static void *p_hh = nullptr, *p_hl = nullptr, *p_b2h = nullptr, *p_b2l = nullptr,
                *p_zx = nullptr, *p_br = nullptr;
    if (!p_hh) {
        cudaGetSymbolAddress(&p_hh, g_hh);
        cudaGetSymbolAddress(&p_hl, g_hl);
        cudaGetSymbolAddress(&p_b2h, g_b2h);
        cudaGetSymbolAddress(&p_b2l, g_b2l);
        cudaGetSymbolAddress(&p_zx, g_zx);
        cudaGetSymbolAddress(&p_br, g_brep);
    }
    gemm_wmma<<<ggrid, 256>>>(
        (const __nv_bfloat16*)p_hh, (const __nv_bfloat16*)p_hl,
        (const __nv_bfloat16*)p_b2h, (const __nv_bfloat16*)p_b2l,
        (const float*)p_br, (float*)p_zx);
    gemm_wmma<<<ggrid, 256>>>(
        (const __nv_bfloat16*)p_hh, (const __nv_bfloat16*)p_hl,
        (const __nv_bfloat16*)p_b2h + 131072, (const __nv_bfloat16*)p_b2l + 131072,
        (const float*)p_br + 8192, (float*)p_zx + (size_t)B_ * T_ * G_);
    lstm_scan<<<128, 512, SWB>>>(1);

    head_kernel<<<64, 128>>>(Wd, bd, Ws, bs, (float*)d_out);
}

// round 16
// speedup vs baseline: 1.3469x; 1.1660x over previous
#include <cuda_runtime.h>
#include <cuda_bf16.h>
#include <mma.h>
#include <math.h>
#include <stdint.h>

using namespace nvcuda;

#define B_ 64
#define T_ 512
#define F_ 64
#define U_ 128
#define G_ 512   // 4*U

#define RGQ 21   // weight quads (4 floats) per thread in registers
#define SGQ 11   // weight quads per thread in smem (RGQ+SGQ = 32)

// ---------------- scratch (static device memory; no allocations) ----------------
__device__ float g_mask[B_ * T_];
__device__ float g_zx[2u * B_ * T_ * G_];               // layer1 then layer2 (reused)
__device__ float g_h2[B_ * 2 * U_];
__device__ float g_wq[4 * G_ * U_];                     // scan weights, quad layout
// bf16 split operands for WMMA GEMMs
__device__ __nv_bfloat16 g_hh[B_ * T_ * 2 * U_];        // h1 hi   [m][256]
__device__ __nv_bfloat16 g_hl[B_ * T_ * 2 * U_];        // h1 lo
__device__ __nv_bfloat16 g_b2h[2 * G_ * 2 * U_];        // W2^T hi [dir][n][256]
__device__ __nv_bfloat16 g_b2l[2 * G_ * 2 * U_];        // W2^T lo
__device__ __nv_bfloat16 g_xh[B_ * T_ * F_];            // x hi    [m][64]
__device__ __nv_bfloat16 g_xl[B_ * T_ * F_];            // x lo
__device__ __nv_bfloat16 g_b1h[2 * G_ * F_];            // W1^T hi [dir][n][64]
__device__ __nv_bfloat16 g_b1l[2 * G_ * F_];            // W1^T lo
__device__ float g_brep2[2 * 16 * G_];                  // layer-2 bias rep [dir][16][512]
__device__ float g_brep1[2 * 16 * G_];                  // layer-1 bias rep

// ---------------- helpers ----------------
#define FMA2(acc, a, b) asm("fma.rn.f32x2 %0, %1, %2, %0;" : "+l"(acc) : "l"(a), "l"(b))

__device__ __forceinline__ float f32x2_sum(unsigned long long v) {
    unsigned lo, hi;
    asm("mov.b64 {%0, %1}, %2;" : "=r"(lo), "=r"(hi) : "l"(v));
    return __uint_as_float(lo) + __uint_as_float(hi);
}
__device__ __forceinline__ unsigned short bf16bits(float f) {
    __nv_bfloat16 b = __float2bfloat16(f);
    return *(unsigned short*)&b;
}

// ---------------- prep: mask + scan quads + W2/W1 splits + bias reps ----------------
__global__ void prep_kernel(const float* __restrict__ x,
                            const float* __restrict__ w1f, const float* __restrict__ w1b,
                            const float* __restrict__ w2f, const float* __restrict__ w2b,
                            const float* __restrict__ w2fi, const float* __restrict__ w2bi,
                            const float* __restrict__ w1fi, const float* __restrict__ w1bi,
                            const float* __restrict__ b2f, const float* __restrict__ b2b,
                            const float* __restrict__ b1f, const float* __restrict__ b1b) {
    int i = blockIdx.x * blockDim.x + threadIdx.x;
    if (i < B_ * T_) {
        const float4* row = (const float4*)(x + (size_t)i * F_);
        bool nz = false;
#pragma unroll
        for (int k = 0; k < F_ / 4; k++) {
            float4 v = row[k];
            nz = nz || (v.x != 0.f) || (v.y != 0.f) || (v.z != 0.f) || (v.w != 0.f);
        }
        g_mask[i] = nz ? 1.f : 0.f;
    }
    int j2 = i - B_ * T_;
    if (j2 >= 0 && j2 < 4 * G_ * U_) {            // scan recurrent weights (quad layout)
        int w = j2 >> 16;
        int r = j2 & 65535;
        int k = r >> 9, col = r & 511;
        const float* src = (w == 0) ? w1f : (w == 1) ? w1b : (w == 2) ? w2f : w2b;
        int u = col & 127, gate = col >> 7;
        int q = k >> 5, g = (k >> 2) & 7, e = k & 3;
        g_wq[w * 65536 + ((gate * 8 + g) * 512 + u * 4 + q) * 4 + e] = src[r];
    }
    int j3 = j2 - 4 * G_ * U_;
    if (j3 >= 0 && j3 < 2 * 2 * U_ * G_) {        // W2^T split: [256][512] x 2 dirs
        int d = j3 >> 17;
        int r = j3 & 131071;
        int k = r >> 9, n = r & 511;
        float v = (d ? w2bi : w2fi)[r];
        __nv_bfloat16 hi = __float2bfloat16(v);
        g_b2h[d * 131072 + n * 256 + k] = hi;
        g_b2l[d * 131072 + n * 256 + k] = __float2bfloat16(v - __bfloat162float(hi));
    }
    int j4 = j3 - 2 * 2 * U_ * G_;
    if (j4 >= 0 && j4 < 2 * G_ * F_) {            // W1^T split: [64][512] x 2 dirs
        int d = j4 >> 15;
        int r = j4 & 32767;
        int k = r >> 9, n = r & 511;
        float v = (d ? w1bi : w1fi)[r];
        __nv_bfloat16 hi = __float2bfloat16(v);
        g_b1h[d * 32768 + n * 64 + k] = hi;
        g_b1l[d * 32768 + n * 64 + k] = __float2bfloat16(v - __bfloat162float(hi));
    }
    int j5 = j4 - 2 * G_ * F_;
    if (j5 >= 0 && j5 < 2 * 16 * G_) {            // layer-2 bias rep
        g_brep2[j5] = ((j5 >> 13) ? b2b : b2f)[j5 & 511];
    }
    int j6 = j5 - 2 * 16 * G_;
    if (j6 >= 0 && j6 < 2 * 16 * G_) {            // layer-1 bias rep
        g_brep1[j6] = ((j6 >> 13) ? b1b : b1f)[j6 & 511];
    }
}

// ---------------- x -> bf16 hi/lo split ----------------
__global__ void convert_x(const float* __restrict__ x) {
    size_t i = (size_t)blockIdx.x * 256 + threadIdx.x;   // over 524288 float4s
    float4 v = ((const float4*)x)[i];
    ushort4 hh, ll;
    hh.x = bf16bits(v.x); hh.y = bf16bits(v.y); hh.z = bf16bits(v.z); hh.w = bf16bits(v.w);
    ll.x = bf16bits(v.x - __bfloat162float(*(__nv_bfloat16*)&hh.x));
    ll.y = bf16bits(v.y - __bfloat162float(*(__nv_bfloat16*)&hh.y));
    ll.z = bf16bits(v.z - __bfloat162float(*(__nv_bfloat16*)&hh.z));
    ll.w = bf16bits(v.w - __bfloat162float(*(__nv_bfloat16*)&hh.w));
    ((ushort4*)g_xh)[i] = hh;
    ((ushort4*)g_xl)[i] = ll;
}

// ---------------- WMMA bf16 3-term GEMM, smem-staged (K parameterized) ----------------
// grid (4 N-tiles, 256 M-tiles), 256 threads = 8 warps (4m x 2n).
// D = Ah*Bh + Ah*Bl + Al*Bh + biasrep ; A [M][K] row-major, B [N][K] (col-major frags).
__global__ __launch_bounds__(256) void gemm_wmma(
    const __nv_bfloat16* __restrict__ Ah, const __nv_bfloat16* __restrict__ Al,
    const __nv_bfloat16* __restrict__ Bh, const __nv_bfloat16* __restrict__ Bl,
    const float* __restrict__ biasrep, float* __restrict__ C, int K) {
    __shared__ __align__(16) __nv_bfloat16 sA[128][72];
    __shared__ __align__(16) __nv_bfloat16 sB[128][72];

    int tid = threadIdx.x;
    int wid = tid >> 5;
    int mw = wid & 3, nw = wid >> 2;
    int mBase = blockIdx.y * 128;
    int nBase = blockIdx.x * 128;
    int mW = mw * 32, nW = nw * 64;
    int kChunks = K >> 6;

    wmma::fragment<wmma::accumulator, 16, 16, 16, float> acc[2][4];
#pragma unroll
    for (int i = 0; i < 2; i++)
#pragma unroll
        for (int j = 0; j < 4; j++)
            wmma::load_matrix_sync(acc[i][j], biasrep + nBase + nW + j * 16, G_,
                                   wmma::mem_row_major);

#pragma unroll
    for (int term = 0; term < 3; term++) {
        const __nv_bfloat16* A = (term == 2) ? Al : Ah;
        const __nv_bfloat16* Bm = (term == 1) ? Bl : Bh;
        for (int kc = 0; kc < kChunks; kc++) {
            int k0 = kc * 64;
#pragma unroll
            for (int s = 0; s < 4; s++) {
                int j = tid + s * 256;
                int row = j >> 3, slot = j & 7;
                *((uint4*)(&sA[row][0]) + slot) =
                    *((const uint4*)(A + (size_t)(mBase + row) * K + k0) + slot);
                *((uint4*)(&sB[row][0]) + slot) =
                    *((const uint4*)(Bm + (size_t)(nBase + row) * K + k0) + slot);
            }
            __syncthreads();
#pragma unroll
            for (int kk = 0; kk < 4; kk++) {
                wmma::fragment<wmma::matrix_a, 16, 16, 16, __nv_bfloat16,
                               wmma::row_major> af[2];
                wmma::fragment<wmma::matrix_b, 16, 16, 16, __nv_bfloat16,
                               wmma::col_major> bf[4];
#pragma unroll
                for (int i = 0; i < 2; i++)
                    wmma::load_matrix_sync(af[i], &sA[mW + i * 16][kk * 16], 72);
#pragma unroll
                for (int j = 0; j < 4; j++)
                    wmma::load_matrix_sync(bf[j], &sB[nW + j * 16][kk * 16], 72);
#pragma unroll
                for (int i = 0; i < 2; i++)
#pragma unroll
                    for (int j = 0; j < 4; j++)
                        wmma::mma_sync(acc[i][j], af[i], bf[j], acc[i][j]);
            }
            __syncthreads();
        }
    }
#pragma unroll
    for (int i = 0; i < 2; i++)
#pragma unroll
        for (int j = 0; j < 4; j++)
            wmma::store_matrix_sync(
                C + (size_t)(mBase + mW + i * 16) * G_ + nBase + nW + j * 16,
                acc[i][j], G_, wmma::mem_row_major);
}

// ---------------- recurrent LSTM scan (R10 core; layer-0 emits bf16 hi/lo h1) ----------------
extern __shared__ float swq[];

__global__ __launch_bounds__(512, 1) void lstm_scan(int layer) {
    int tid = threadIdx.x;
    int dir = blockIdx.x >> 6;
    int b = blockIdx.x & 63;
    int seg = layer * 2 + dir;
    int u = tid >> 2, q = tid & 3;

    __shared__ __align__(16) float hbuf[2][544];

    {
        const float4* src = (const float4*)(g_wq + (size_t)seg * 65536 + RGQ * 2048);
        float4* dst = (float4*)swq;
        for (int j = tid; j < SGQ * 512; j += 512) dst[j] = src[j];
    }
    ulonglong2 wreg[RGQ];
    {
        const float* wb = g_wq + (size_t)seg * 65536 + tid * 4;
#pragma unroll
        for (int m = 0; m < RGQ; m++) wreg[m] = *(const ulonglong2*)(wb + m * 2048);
    }
    for (int j = tid; j < 1088; j += 512) ((float*)hbuf)[j] = 0.f;
    __syncthreads();

    const float* zc = g_zx + ((size_t)dir * B_ + b) * T_ * G_ + q * 128 + u;
    const int mb = b * T_;
    float zpre, mpre;
    {
        int te0 = dir ? (T_ - 1) : 0;
        zpre = zc[(size_t)te0 * G_];
        mpre = g_mask[mb + te0];
    }
    float c_state = 0.f, hprev = 0.f;

    for (int t = 0; t < T_; t++) {
        int te = dir ? (T_ - 1 - t) : t;
        int cur = t & 1, nxt = cur ^ 1;

        float znext = 0.f, mnext = 0.f;
        if (t + 1 < T_) {
            int tn = dir ? (T_ - 2 - t) : (t + 1);
            znext = zc[(size_t)tn * G_];
            mnext = g_mask[mb + tn];
        }

        const float* hc = &hbuf[cur][q * 168];
        const float* swp = swq + tid * 4;
        unsigned long long acc[4] = {0ull, 0ull, 0ull, 0ull};
#pragma unroll
        for (int g = 0; g < 8; g++) {
            ulonglong2 h = *(const ulonglong2*)(hc + 4 * g);
#pragma unroll
            for (int gate = 0; gate < 4; gate++) {
                int m = gate * 8 + g;
                ulonglong2 w;
                if (m < RGQ) w = wreg[m];
                else w = *(const ulonglong2*)(swp + (m - RGQ) * 2048);
                FMA2(acc[gate], w.x, h.x);
                FMA2(acc[gate], w.y, h.y);
            }
        }
        float v0 = f32x2_sum(acc[0]);
        float v1 = f32x2_sum(acc[1]);
        float v2 = f32x2_sum(acc[2]);
        float v3 = f32x2_sum(acc[3]);
        v0 += (q == 0) ? zpre : 0.f;
        v1 += (q == 1) ? zpre : 0.f;
        v2 += (q == 2) ? zpre : 0.f;
        v3 += (q == 3) ? zpre : 0.f;

        v0 += __shfl_xor_sync(0xFFFFFFFFu, v0, 1);
        v1 += __shfl_xor_sync(0xFFFFFFFFu, v1, 1);
        v2 += __shfl_xor_sync(0xFFFFFFFFu, v2, 1);
        v3 += __shfl_xor_sync(0xFFFFFFFFu, v3, 1);
        v0 += __shfl_xor_sync(0xFFFFFFFFu, v0, 2);
        v1 += __shfl_xor_sync(0xFFFFFFFFu, v1, 2);
        v2 += __shfl_xor_sync(0xFFFFFFFFu, v2, 2);
        v3 += __shfl_xor_sync(0xFFFFFFFFu, v3, 2);

        float si = 1.f / (1.f + __expf(-v0));
        float sf = 1.f / (1.f + __expf(-v1));
        float so = 1.f / (1.f + __expf(-v3));
        float cn = sf * c_state + si * tanhf(v2);
        float hn = so * tanhf(cn);
        bool mm = (mpre != 0.f);
        c_state = mm ? cn : c_state;
        float hnew = mm ? hn : hprev;
        hbuf[nxt][q * 136 + u] = hnew;
        if (layer == 0) {
            // lanes 1/2 emit the bf16 hi/lo split of h1 directly (replaces convert_h1)
            size_t idx = ((size_t)b * T_ + te) * (2 * U_) + dir * U_ + u;
            if (q == 1) {
                g_hh[idx] = __float2bfloat16(hnew);
            } else if (q == 2) {
                __nv_bfloat16 hb = __float2bfloat16(hnew);
                g_hl[idx] = __float2bfloat16(hnew - __bfloat162float(hb));
            }
        }
        hprev = hnew;
        zpre = znext;
        mpre = mnext;
        __syncthreads();
    }

    if (layer == 1 && q == 0)
        g_h2[b * (2 * U_) + dir * U_ + u] = hprev;
}

// ---------------- head ----------------
__global__ __launch_bounds__(128) void head_kernel(
    const float* __restrict__ Wd, const float* __restrict__ bd,
    const float* __restrict__ Ws, const float* __restrict__ bs,
    float* __restrict__ out) {
    int b = blockIdx.x, u = threadIdx.x;
    float acc = bd[u];
    const float* h2 = g_h2 + b * (2 * U_);
#pragma unroll 8
    for (int j = 0; j < 2 * U_; j++) acc = fmaf(h2[j], Wd[j * U_ + u], acc);
    acc = fmaxf(acc, 0.f);
    float s = acc * Ws[u];
    __shared__ float red[128];
    red[u] = s;
    __syncthreads();
    for (int off = 64; off; off >>= 1) {
        if (u < off) red[u] += red[u + off];
        __syncthreads();
    }
    if (u == 0) out[b] = 1.f / (1.f + expf(-(red[0] + bs[0])));
}

// ---------------- launch ----------------
extern "C" void kernel_launch(void* const* d_in, const int* in_sizes, int n_in,
                              void* d_out, int out_size) {
    const float* x    = (const float*)d_in[0];
    const float* W1fi = (const float*)d_in[1];
    const float* W1fh = (const float*)d_in[2];
    const float* b1f  = (const float*)d_in[3];
    const float* W1bi = (const float*)d_in[4];
    const float* W1bh = (const float*)d_in[5];
    const float* b1b  = (const float*)d_in[6];
    const float* W2fi = (const float*)d_in[7];
    const float* W2fh = (const float*)d_in[8];
    const float* b2f  = (const float*)d_in[9];
    const float* W2bi = (const float*)d_in[10];
    const float* W2bh = (const float*)d_in[11];
    const float* b2b  = (const float*)d_in[12];
    const float* Wd   = (const float*)d_in[13];
    const float* bd   = (const float*)d_in[14];
    const float* Ws   = (const float*)d_in[15];
    const float* bs   = (const float*)d_in[16];

    const int SWB = SGQ * 2048 * 4;
    static int attrDone = 0;
    if (!attrDone) {
        cudaFuncSetAttribute(lstm_scan, cudaFuncAttributeMaxDynamicSharedMemorySize, SWB);
        attrDone = 1;
    }

    int prepWork = B_ * T_ + 4 * G_ * U_ + 2 * 2 * U_ * G_ + 2 * G_ * F_ +
                   2 * 16 * G_ + 2 * 16 * G_;
    prep_kernel<<<(prepWork + 255) / 256, 256>>>(x, W1fh, W1bh, W2fh, W2bh,
                                                 W2fi, W2bi, W1fi, W1bi,
                                                 b2f, b2b, b1f, b1b);
    convert_x<<<2048, 256>>>(x);

    static void *p_hh = nullptr, *p_hl = nullptr, *p_b2h = nullptr, *p_b2l = nullptr,
                *p_zx = nullptr, *p_br2 = nullptr, *p_br1 = nullptr,
                *p_xh = nullptr, *p_xl = nullptr, *p_b1h = nullptr, *p_b1l = nullptr;
    if (!p_hh) {
        cudaGetSymbolAddress(&p_hh, g_hh);
        cudaGetSymbolAddress(&p_hl, g_hl);
        cudaGetSymbolAddress(&p_b2h, g_b2h);
        cudaGetSymbolAddress(&p_b2l, g_b2l);
        cudaGetSymbolAddress(&p_zx, g_zx);
        cudaGetSymbolAddress(&p_br2, g_brep2);
        cudaGetSymbolAddress(&p_br1, g_brep1);
        cudaGetSymbolAddress(&p_xh, g_xh);
        cudaGetSymbolAddress(&p_xl, g_xl);
        cudaGetSymbolAddress(&p_b1h, g_b1h);
        cudaGetSymbolAddress(&p_b1l, g_b1l);
    }
    dim3 ggrid(G_ / 128, (B_ * T_) / 128);  // (4, 256)
    size_t zxHalf = (size_t)B_ * T_ * G_;

    // layer-1 input projections (WMMA 3-term, K=64)
    gemm_wmma<<<ggrid, 256>>>(
        (const __nv_bfloat16*)p_xh, (const __nv_bfloat16*)p_xl,
        (const __nv_bfloat16*)p_b1h, (const __nv_bfloat16*)p_b1l,
        (const float*)p_br1, (float*)p_zx, F_);
    gemm_wmma<<<ggrid, 256>>>(
        (const __nv_bfloat16*)p_xh, (const __nv_bfloat16*)p_xl,
        (const __nv_bfloat16*)p_b1h + 32768, (const __nv_bfloat16*)p_b1l + 32768,
        (const float*)p_br1 + 8192, (float*)p_zx + zxHalf, F_);
    lstm_scan<<<128, 512, SWB>>>(0);

    // layer-2 input projections (WMMA 3-term, K=256); h1 hi/lo emitted by scan 0
    gemm_wmma<<<ggrid, 256>>>(
        (const __nv_bfloat16*)p_hh, (const __nv_bfloat16*)p_hl,
        (const __nv_bfloat16*)p_b2h, (const __nv_bfloat16*)p_b2l,
        (const float*)p_br2, (float*)p_zx, 2 * U_);
    gemm_wmma<<<ggrid, 256>>>(
        (const __nv_bfloat16*)p_hh, (const __nv_bfloat16*)p_hl,
        (const __nv_bfloat16*)p_b2h + 131072, (const __nv_bfloat16*)p_b2l + 131072,
        (const float*)p_br2 + 8192, (float*)p_zx + zxHalf, 2 * U_);
    lstm_scan<<<128, 512, SWB>>>(1);

    head_kernel<<<64, 128>>>(Wd, bd, Ws, bs, (float*)d_out);
}

// round 17
// speedup vs baseline: 1.4573x; 1.0819x over previous
#include <cuda_runtime.h>
#include <cuda_bf16.h>
#include <mma.h>
#include <math.h>
#include <stdint.h>

using namespace nvcuda;

#define B_ 64
#define T_ 512
#define F_ 64
#define U_ 128
#define G_ 512   // 4*U

#define RGQ 21   // weight quads (4 floats) per thread in registers
#define SGQ 11   // weight quads per thread in smem (RGQ+SGQ = 32)

// ---------------- scratch (static device memory; no allocations) ----------------
__device__ float g_mask[B_ * T_];
__device__ float g_zx[2u * B_ * T_ * G_];               // layer1 then layer2 (reused)
__device__ float g_h2[B_ * 2 * U_];
__device__ float g_wq[4 * G_ * U_];                     // scan weights, quad layout
// bf16 split operands for WMMA GEMMs
__device__ __nv_bfloat16 g_hh[B_ * T_ * 2 * U_];        // h1 hi   [m][256]
__device__ __nv_bfloat16 g_hl[B_ * T_ * 2 * U_];        // h1 lo
__device__ __nv_bfloat16 g_b2h[2 * G_ * 2 * U_];        // W2^T hi [dir][n][256]
__device__ __nv_bfloat16 g_b2l[2 * G_ * 2 * U_];        // W2^T lo
__device__ __nv_bfloat16 g_xh[B_ * T_ * F_];            // x hi    [m][64]
__device__ __nv_bfloat16 g_xl[B_ * T_ * F_];            // x lo
__device__ __nv_bfloat16 g_b1h[2 * G_ * F_];            // W1^T hi [dir][n][64]
__device__ __nv_bfloat16 g_b1l[2 * G_ * F_];            // W1^T lo
__device__ float g_brep2[2 * 16 * G_];                  // layer-2 bias rep [dir][16][512]
__device__ float g_brep1[2 * 16 * G_];                  // layer-1 bias rep

// ---------------- helpers ----------------
#define FMA2(acc, a, b) asm("fma.rn.f32x2 %0, %1, %2, %0;" : "+l"(acc) : "l"(a), "l"(b))

__device__ __forceinline__ float f32x2_sum(unsigned long long v) {
    unsigned lo, hi;
    asm("mov.b64 {%0, %1}, %2;" : "=r"(lo), "=r"(hi) : "l"(v));
    return __uint_as_float(lo) + __uint_as_float(hi);
}
__device__ __forceinline__ unsigned short bf16bits(float f) {
    __nv_bfloat16 b = __float2bfloat16(f);
    return *(unsigned short*)&b;
}
__device__ __forceinline__ float rcpa(float d) {
    float r;
    asm("rcp.approx.f32 %0, %1;" : "=f"(r) : "f"(d));
    return r;
}
__device__ __forceinline__ float sig_fast(float x) {
    return rcpa(1.f + __expf(-x));
}
__device__ __forceinline__ float tanh_fast(float x) {
    // tanh(x) = 1 - 2/(exp(2x)+1); exp->inf => rcp->0 => 1 ; exp->0 => -1
    return 1.f - 2.f * rcpa(__expf(2.f * x) + 1.f);
}

// ---------------- prep: mask + scan quads + W2/W1 splits + bias reps ----------------
__global__ void prep_kernel(const float* __restrict__ x,
                            const float* __restrict__ w1f, const float* __restrict__ w1b,
                            const float* __restrict__ w2f, const float* __restrict__ w2b,
                            const float* __restrict__ w2fi, const float* __restrict__ w2bi,
                            const float* __restrict__ w1fi, const float* __restrict__ w1bi,
                            const float* __restrict__ b2f, const float* __restrict__ b2b,
                            const float* __restrict__ b1f, const float* __restrict__ b1b) {
    int i = blockIdx.x * blockDim.x + threadIdx.x;
    if (i < B_ * T_) {
        const float4* row = (const float4*)(x + (size_t)i * F_);
        bool nz = false;
#pragma unroll
        for (int k = 0; k < F_ / 4; k++) {
            float4 v = row[k];
            nz = nz || (v.x != 0.f) || (v.y != 0.f) || (v.z != 0.f) || (v.w != 0.f);
        }
        g_mask[i] = nz ? 1.f : 0.f;
    }
    int j2 = i - B_ * T_;
    if (j2 >= 0 && j2 < 4 * G_ * U_) {            // scan recurrent weights (quad layout)
        int w = j2 >> 16;
        int r = j2 & 65535;
        int k = r >> 9, col = r & 511;
        const float* src = (w == 0) ? w1f : (w == 1) ? w1b : (w == 2) ? w2f : w2b;
        int u = col & 127, gate = col >> 7;
        int q = k >> 5, g = (k >> 2) & 7, e = k & 3;
        g_wq[w * 65536 + ((gate * 8 + g) * 512 + u * 4 + q) * 4 + e] = src[r];
    }
    int j3 = j2 - 4 * G_ * U_;
    if (j3 >= 0 && j3 < 2 * 2 * U_ * G_) {        // W2^T split: [256][512] x 2 dirs
        int d = j3 >> 17;
        int r = j3 & 131071;
        int k = r >> 9, n = r & 511;
        float v = (d ? w2bi : w2fi)[r];
        __nv_bfloat16 hi = __float2bfloat16(v);
        g_b2h[d * 131072 + n * 256 + k] = hi;
        g_b2l[d * 131072 + n * 256 + k] = __float2bfloat16(v - __bfloat162float(hi));
    }
    int j4 = j3 - 2 * 2 * U_ * G_;
    if (j4 >= 0 && j4 < 2 * G_ * F_) {            // W1^T split: [64][512] x 2 dirs
        int d = j4 >> 15;
        int r = j4 & 32767;
        int k = r >> 9, n = r & 511;
        float v = (d ? w1bi : w1fi)[r];
        __nv_bfloat16 hi = __float2bfloat16(v);
        g_b1h[d * 32768 + n * 64 + k] = hi;
        g_b1l[d * 32768 + n * 64 + k] = __float2bfloat16(v - __bfloat162float(hi));
    }
    int j5 = j4 - 2 * G_ * F_;
    if (j5 >= 0 && j5 < 2 * 16 * G_) {            // layer-2 bias rep
        g_brep2[j5] = ((j5 >> 13) ? b2b : b2f)[j5 & 511];
    }
    int j6 = j5 - 2 * 16 * G_;
    if (j6 >= 0 && j6 < 2 * 16 * G_) {            // layer-1 bias rep
        g_brep1[j6] = ((j6 >> 13) ? b1b : b1f)[j6 & 511];
    }
}

// ---------------- x -> bf16 hi/lo split ----------------
__global__ void convert_x(const float* __restrict__ x) {
    size_t i = (size_t)blockIdx.x * 256 + threadIdx.x;   // over 524288 float4s
    float4 v = ((const float4*)x)[i];
    ushort4 hh, ll;
    hh.x = bf16bits(v.x); hh.y = bf16bits(v.y); hh.z = bf16bits(v.z); hh.w = bf16bits(v.w);
    ll.x = bf16bits(v.x - __bfloat162float(*(__nv_bfloat16*)&hh.x));
    ll.y = bf16bits(v.y - __bfloat162float(*(__nv_bfloat16*)&hh.y));
    ll.z = bf16bits(v.z - __bfloat162float(*(__nv_bfloat16*)&hh.z));
    ll.w = bf16bits(v.w - __bfloat162float(*(__nv_bfloat16*)&hh.w));
    ((ushort4*)g_xh)[i] = hh;
    ((ushort4*)g_xl)[i] = ll;
}

// ---------------- WMMA bf16 3-term GEMM, smem-staged (K parameterized) ----------------
__global__ __launch_bounds__(256) void gemm_wmma(
    const __nv_bfloat16* __restrict__ Ah, const __nv_bfloat16* __restrict__ Al,
    const __nv_bfloat16* __restrict__ Bh, const __nv_bfloat16* __restrict__ Bl,
    const float* __restrict__ biasrep, float* __restrict__ C, int K) {
    __shared__ __align__(16) __nv_bfloat16 sA[128][72];
    __shared__ __align__(16) __nv_bfloat16 sB[128][72];

    int tid = threadIdx.x;
    int wid = tid >> 5;
    int mw = wid & 3, nw = wid >> 2;
    int mBase = blockIdx.y * 128;
    int nBase = blockIdx.x * 128;
    int mW = mw * 32, nW = nw * 64;
    int kChunks = K >> 6;

    wmma::fragment<wmma::accumulator, 16, 16, 16, float> acc[2][4];
#pragma unroll
    for (int i = 0; i < 2; i++)
#pragma unroll
        for (int j = 0; j < 4; j++)
            wmma::load_matrix_sync(acc[i][j], biasrep + nBase + nW + j * 16, G_,
                                   wmma::mem_row_major);

#pragma unroll
    for (int term = 0; term < 3; term++) {
        const __nv_bfloat16* A = (term == 2) ? Al : Ah;
        const __nv_bfloat16* Bm = (term == 1) ? Bl : Bh;
        for (int kc = 0; kc < kChunks; kc++) {
            int k0 = kc * 64;
#pragma unroll
            for (int s = 0; s < 4; s++) {
                int j = tid + s * 256;
                int row = j >> 3, slot = j & 7;
                *((uint4*)(&sA[row][0]) + slot) =
                    *((const uint4*)(A + (size_t)(mBase + row) * K + k0) + slot);
                *((uint4*)(&sB[row][0]) + slot) =
                    *((const uint4*)(Bm + (size_t)(nBase + row) * K + k0) + slot);
            }
            __syncthreads();
#pragma unroll
            for (int kk = 0; kk < 4; kk++) {
                wmma::fragment<wmma::matrix_a, 16, 16, 16, __nv_bfloat16,
                               wmma::row_major> af[2];
                wmma::fragment<wmma::matrix_b, 16, 16, 16, __nv_bfloat16,
                               wmma::col_major> bf[4];
#pragma unroll
                for (int i = 0; i < 2; i++)
                    wmma::load_matrix_sync(af[i], &sA[mW + i * 16][kk * 16], 72);
#pragma unroll
                for (int j = 0; j < 4; j++)
                    wmma::load_matrix_sync(bf[j], &sB[nW + j * 16][kk * 16], 72);
#pragma unroll
                for (int i = 0; i < 2; i++)
#pragma unroll
                    for (int j = 0; j < 4; j++)
                        wmma::mma_sync(acc[i][j], af[i], bf[j], acc[i][j]);
            }
            __syncthreads();
        }
    }
#pragma unroll
    for (int i = 0; i < 2; i++)
#pragma unroll
        for (int j = 0; j < 4; j++)
            wmma::store_matrix_sync(
                C + (size_t)(mBase + mW + i * 16) * G_ + nBase + nW + j * 16,
                acc[i][j], G_, wmma::mem_row_major);
}

// ---------------- recurrent LSTM scan (fast MUFU cell; layer-0 emits bf16 h1) ----------------
extern __shared__ float swq[];

__global__ __launch_bounds__(512, 1) void lstm_scan(int layer) {
    int tid = threadIdx.x;
    int dir = blockIdx.x >> 6;
    int b = blockIdx.x & 63;
    int seg = layer * 2 + dir;
    int u = tid >> 2, q = tid & 3;

    __shared__ __align__(16) float hbuf[2][544];

    {
        const float4* src = (const float4*)(g_wq + (size_t)seg * 65536 + RGQ * 2048);
        float4* dst = (float4*)swq;
        for (int j = tid; j < SGQ * 512; j += 512) dst[j] = src[j];
    }
    ulonglong2 wreg[RGQ];
    {
        const float* wb = g_wq + (size_t)seg * 65536 + tid * 4;
#pragma unroll
        for (int m = 0; m < RGQ; m++) wreg[m] = *(const ulonglong2*)(wb + m * 2048);
    }
    for (int j = tid; j < 1088; j += 512) ((float*)hbuf)[j] = 0.f;
    __syncthreads();

    const float* zc = g_zx + ((size_t)dir * B_ + b) * T_ * G_ + q * 128 + u;
    const int mb = b * T_;
    float zpre, mpre;
    {
        int te0 = dir ? (T_ - 1) : 0;
        zpre = zc[(size_t)te0 * G_];
        mpre = g_mask[mb + te0];
    }
    float c_state = 0.f, hprev = 0.f;

    for (int t = 0; t < T_; t++) {
        int te = dir ? (T_ - 1 - t) : t;
        int cur = t & 1, nxt = cur ^ 1;

        float znext = 0.f, mnext = 0.f;
        if (t + 1 < T_) {
            int tn = dir ? (T_ - 2 - t) : (t + 1);
            znext = zc[(size_t)tn * G_];
            mnext = g_mask[mb + tn];
        }

        const float* hc = &hbuf[cur][q * 168];
        const float* swp = swq + tid * 4;
        unsigned long long acc[4] = {0ull, 0ull, 0ull, 0ull};
#pragma unroll
        for (int g = 0; g < 8; g++) {
            ulonglong2 h = *(const ulonglong2*)(hc + 4 * g);
#pragma unroll
            for (int gate = 0; gate < 4; gate++) {
                int m = gate * 8 + g;
                ulonglong2 w;
                if (m < RGQ) w = wreg[m];
                else w = *(const ulonglong2*)(swp + (m - RGQ) * 2048);
                FMA2(acc[gate], w.x, h.x);
                FMA2(acc[gate], w.y, h.y);
            }
        }
        float v0 = f32x2_sum(acc[0]);
        float v1 = f32x2_sum(acc[1]);
        float v2 = f32x2_sum(acc[2]);
        float v3 = f32x2_sum(acc[3]);
        v0 += (q == 0) ? zpre : 0.f;
        v1 += (q == 1) ? zpre : 0.f;
        v2 += (q == 2) ? zpre : 0.f;
        v3 += (q == 3) ? zpre : 0.f;

        v0 += __shfl_xor_sync(0xFFFFFFFFu, v0, 1);
        v1 += __shfl_xor_sync(0xFFFFFFFFu, v1, 1);
        v2 += __shfl_xor_sync(0xFFFFFFFFu, v2, 1);
        v3 += __shfl_xor_sync(0xFFFFFFFFu, v3, 1);
        v0 += __shfl_xor_sync(0xFFFFFFFFu, v0, 2);
        v1 += __shfl_xor_sync(0xFFFFFFFFu, v1, 2);
        v2 += __shfl_xor_sync(0xFFFFFFFFu, v2, 2);
        v3 += __shfl_xor_sync(0xFFFFFFFFu, v3, 2);

        // fast MUFU cell (rcp.approx + __expf; saturation-safe)
        float si = sig_fast(v0);
        float sf = sig_fast(v1);
        float so = sig_fast(v3);
        float cn = sf * c_state + si * tanh_fast(v2);
        float hn = so * tanh_fast(cn);
        bool mm = (mpre != 0.f);
        c_state = mm ? cn : c_state;
        float hnew = mm ? hn : hprev;
        hbuf[nxt][q * 136 + u] = hnew;
        if (layer == 0) {
            size_t idx = ((size_t)b * T_ + te) * (2 * U_) + dir * U_ + u;
            if (q == 1) {
                g_hh[idx] = __float2bfloat16(hnew);
            } else if (q == 2) {
                __nv_bfloat16 hb = __float2bfloat16(hnew);
                g_hl[idx] = __float2bfloat16(hnew - __bfloat162float(hb));
            }
        }
        hprev = hnew;
        zpre = znext;
        mpre = mnext;
        __syncthreads();
    }

    if (layer == 1 && q == 0)
        g_h2[b * (2 * U_) + dir * U_ + u] = hprev;
}

// ---------------- head ----------------
__global__ __launch_bounds__(128) void head_kernel(
    const float* __restrict__ Wd, const float* __restrict__ bd,
    const float* __restrict__ Ws, const float* __restrict__ bs,
    float* __restrict__ out) {
    int b = blockIdx.x, u = threadIdx.x;
    float acc = bd[u];
    const float* h2 = g_h2 + b * (2 * U_);
#pragma unroll 8
    for (int j = 0; j < 2 * U_; j++) acc = fmaf(h2[j], Wd[j * U_ + u], acc);
    acc = fmaxf(acc, 0.f);
    float s = acc * Ws[u];
    __shared__ float red[128];
    red[u] = s;
    __syncthreads();
    for (int off = 64; off; off >>= 1) {
        if (u < off) red[u] += red[u + off];
        __syncthreads();
    }
    if (u == 0) out[b] = 1.f / (1.f + expf(-(red[0] + bs[0])));
}

// ---------------- launch ----------------
extern "C" void kernel_launch(void* const* d_in, const int* in_sizes, int n_in,
                              void* d_out, int out_size) {
    const float* x    = (const float*)d_in[0];
    const float* W1fi = (const float*)d_in[1];
    const float* W1fh = (const float*)d_in[2];
    const float* b1f  = (const float*)d_in[3];
    const float* W1bi = (const float*)d_in[4];
    const float* W1bh = (const float*)d_in[5];
    const float* b1b  = (const float*)d_in[6];
    const float* W2fi = (const float*)d_in[7];
    const float* W2fh = (const float*)d_in[8];
    const float* b2f  = (const float*)d_in[9];
    const float* W2bi = (const float*)d_in[10];
    const float* W2bh = (const float*)d_in[11];
    const float* b2b  = (const float*)d_in[12];
    const float* Wd   = (const float*)d_in[13];
    const float* bd   = (const float*)d_in[14];
    const float* Ws   = (const float*)d_in[15];
    const float* bs   = (const float*)d_in[16];

    const int SWB = SGQ * 2048 * 4;
    static int attrDone = 0;
    if (!attrDone) {
        cudaFuncSetAttribute(lstm_scan, cudaFuncAttributeMaxDynamicSharedMemorySize, SWB);
        attrDone = 1;
    }

    int prepWork = B_ * T_ + 4 * G_ * U_ + 2 * 2 * U_ * G_ + 2 * G_ * F_ +
                   2 * 16 * G_ + 2 * 16 * G_;
    prep_kernel<<<(prepWork + 255) / 256, 256>>>(x, W1fh, W1bh, W2fh, W2bh,
                                                 W2fi, W2bi, W1fi, W1bi,
                                                 b2f, b2b, b1f, b1b);
    convert_x<<<2048, 256>>>(x);

    static void *p_hh = nullptr, *p_hl = nullptr, *p_b2h = nullptr, *p_b2l = nullptr,
                *p_zx = nullptr, *p_br2 = nullptr, *p_br1 = nullptr,
                *p_xh = nullptr, *p_xl = nullptr, *p_b1h = nullptr, *p_b1l = nullptr;
    if (!p_hh) {
        cudaGetSymbolAddress(&p_hh, g_hh);
        cudaGetSymbolAddress(&p_hl, g_hl);
        cudaGetSymbolAddress(&p_b2h, g_b2h);
        cudaGetSymbolAddress(&p_b2l, g_b2l);
        cudaGetSymbolAddress(&p_zx, g_zx);
        cudaGetSymbolAddress(&p_br2, g_brep2);
        cudaGetSymbolAddress(&p_br1, g_brep1);
        cudaGetSymbolAddress(&p_xh, g_xh);
        cudaGetSymbolAddress(&p_xl, g_xl);
        cudaGetSymbolAddress(&p_b1h, g_b1h);
        cudaGetSymbolAddress(&p_b1l, g_b1l);
    }
    dim3 ggrid(G_ / 128, (B_ * T_) / 128);  // (4, 256)
    size_t zxHalf = (size_t)B_ * T_ * G_;

    // layer-1 input projections (WMMA 3-term, K=64)
    gemm_wmma<<<ggrid, 256>>>(
        (const __nv_bfloat16*)p_xh, (const __nv_bfloat16*)p_xl,
        (const __nv_bfloat16*)p_b1h, (const __nv_bfloat16*)p_b1l,
        (const float*)p_br1, (float*)p_zx, F_);
    gemm_wmma<<<ggrid, 256>>>(
        (const __nv_bfloat16*)p_xh, (const __nv_bfloat16*)p_xl,
        (const __nv_bfloat16*)p_b1h + 32768, (const __nv_bfloat16*)p_b1l + 32768,
        (const float*)p_br1 + 8192, (float*)p_zx + zxHalf, F_);
    lstm_scan<<<128, 512, SWB>>>(0);

    // layer-2 input projections (WMMA 3-term, K=256); h1 hi/lo emitted by scan 0
    gemm_wmma<<<ggrid, 256>>>(
        (const __nv_bfloat16*)p_hh, (const __nv_bfloat16*)p_hl,
        (const __nv_bfloat16*)p_b2h, (const __nv_bfloat16*)p_b2l,
        (const float*)p_br2, (float*)p_zx, 2 * U_);
    gemm_wmma<<<ggrid, 256>>>(
        (const __nv_bfloat16*)p_hh, (const __nv_bfloat16*)p_hl,
        (const __nv_bfloat16*)p_b2h + 131072, (const __nv_bfloat16*)p_b2l + 131072,
        (const float*)p_br2 + 8192, (float*)p_zx + zxHalf, 2 * U_);
    lstm_scan<<<128, 512, SWB>>>(1);

    head_kernel<<<64, 128>>>(Wd, bd, Ws, bs, (float*)d_out);
}